// round 16
// baseline (speedup 1.0000x reference)
#include <cuda_runtime.h>
#include <cuda_fp16.h>
#include <math.h>
#include <stdint.h>

// Problem dims
#define BB 64
#define NI 512
#define NQ 128
#define DD 640
#define DH 1280
#define NEGV (-65504.0f)

// ---------------- scratch ----------------
__device__ float  g_ST[BB * NQ * NI];
__device__ float  g_atti[BB * NI];
__device__ float  g_attl[BB * NQ];
__device__ float  g_w1[BB * NQ];
__device__ float  g_w2v[BB * NI];
__device__ float  g_pool[2 * BB * DD];
__device__ __half g_ih[BB * NI * DD];
__device__ __half g_qh[BB * NQ * DD];
__device__ __half g_ihT[BB * DD * NI];
__device__ __half g_P1h[BB * NI * NQ];
__device__ __half g_P2h[BB * NQ * NI];
__device__ __half g_latth[BB * NQ * DD];
__device__ __half g_qW1T[BB * DH * NQ];
__device__ __half g_WT0[DH * DD];
__device__ __half g_WT1[DH * DD];

__device__ __forceinline__ uint32_t smem_u32(const void* p)
{
    uint32_t a;
    asm("{ .reg .u64 t; cvta.to.shared.u64 t, %1; cvt.u32.u64 %0, t; }" : "=r"(a) : "l"(p));
    return a;
}
__device__ __forceinline__ void ldmx4(uint32_t r[4], uint32_t addr)
{
    asm volatile("ldmatrix.sync.aligned.m8n8.x4.shared.b16 {%0,%1,%2,%3}, [%4];"
                 : "=r"(r[0]), "=r"(r[1]), "=r"(r[2]), "=r"(r[3]) : "r"(addr));
}
__device__ __forceinline__ void mma_f16(float c[4], const uint32_t a[4],
                                        uint32_t b0, uint32_t b1)
{
    asm volatile(
        "mma.sync.aligned.m16n8k16.row.col.f32.f16.f16.f32 "
        "{%0,%1,%2,%3}, {%4,%5,%6,%7}, {%8,%9}, {%0,%1,%2,%3};"
        : "+f"(c[0]), "+f"(c[1]), "+f"(c[2]), "+f"(c[3])
        : "r"(a[0]), "r"(a[1]), "r"(a[2]), "r"(a[3]), "r"(b0), "r"(b1));
}
__device__ __forceinline__ void mma_h16(uint32_t d[2], const uint32_t a[4],
                                        uint32_t b0, uint32_t b1)
{
    asm volatile(
        "mma.sync.aligned.m16n8k16.row.col.f16.f16.f16.f16 "
        "{%0,%1}, {%2,%3,%4,%5}, {%6,%7}, {%0,%1};"
        : "+r"(d[0]), "+r"(d[1])
        : "r"(a[0]), "r"(a[1]), "r"(a[2]), "r"(a[3]), "r"(b0), "r"(b1));
}
__device__ __forceinline__ void cp16(uint32_t dst, const void* src)
{
    asm volatile("cp.async.ca.shared.global [%0], [%1], 16;" :: "r"(dst), "l"(src));
}
#define CP_COMMIT() asm volatile("cp.async.commit_group;" ::: "memory")
#define CP_WAIT0()  asm volatile("cp.async.wait_group 0;" ::: "memory")

#define SSTR 72
#define STAGE_B (128 * SSTR * 2)
#define STAGE2_B (2 * STAGE_B)
#define HG_SMEM (2 * STAGE2_B)

// single-stage K=128 layout: stride 136 halfs (272 B)
#define SSTR2 136
#define A128_B (128 * SSTR2 * 2)      // 34816 B

// ---------- 2-stage cp.async mainloops (128x128 tile, BK=64) ----------
__device__ __forceinline__ void hg_loop_f32(uint32_t smb, const __half* __restrict__ A,
                                            const __half* __restrict__ BT, int K,
                                            int m0, int n0, float acc[4][4][4])
{
    const int tid  = threadIdx.x;
    const int lane = tid & 31;
    const int wid  = tid >> 5;
    const int warp_m = wid & 1, warp_n = wid >> 1;
    const int srow = tid >> 2;
    const int sco  = (tid & 3) * 16;
    const __half* Ag0 = A + (long)(m0 + srow) * K + sco;
    const __half* Ag1 = A + (long)(m0 + srow + 64) * K + sco;
    const __half* Bg0 = BT + (long)(n0 + srow) * K + sco;
    const __half* Bg1 = BT + (long)(n0 + srow + 64) * K + sco;
    const uint32_t dA0 = srow * (SSTR * 2) + (tid & 3) * 32;
    const uint32_t dA1 = (srow + 64) * (SSTR * 2) + (tid & 3) * 32;
    const uint32_t aRowOff = (warp_m * 64 + (lane & 15)) * (SSTR * 2) + (lane >> 4) * 16;
    const uint32_t bRowOff = STAGE_B + (warp_n * 32 + (lane & 15)) * (SSTR * 2) + (lane >> 4) * 16;

#pragma unroll
    for (int i = 0; i < 4; i++)
#pragma unroll
        for (int j = 0; j < 4; j++)
#pragma unroll
            for (int r = 0; r < 4; r++) acc[i][j][r] = 0.f;

    const int nc = K >> 6;
    {
        cp16(smb + dA0, Ag0);            cp16(smb + dA0 + 16, Ag0 + 8);
        cp16(smb + dA1, Ag1);            cp16(smb + dA1 + 16, Ag1 + 8);
        cp16(smb + STAGE_B + dA0, Bg0);  cp16(smb + STAGE_B + dA0 + 16, Bg0 + 8);
        cp16(smb + STAGE_B + dA1, Bg1);  cp16(smb + STAGE_B + dA1 + 16, Bg1 + 8);
        CP_COMMIT();
    }
#pragma unroll 1
    for (int c = 0; c < nc; ++c) {
        CP_WAIT0();
        __syncthreads();
        if (c + 1 < nc) {
            const uint32_t sb = smb + ((c + 1) & 1) * STAGE2_B;
            const long ko = (long)(c + 1) * 64;
            cp16(sb + dA0, Ag0 + ko);            cp16(sb + dA0 + 16, Ag0 + ko + 8);
            cp16(sb + dA1, Ag1 + ko);            cp16(sb + dA1 + 16, Ag1 + ko + 8);
            cp16(sb + STAGE_B + dA0, Bg0 + ko);  cp16(sb + STAGE_B + dA0 + 16, Bg0 + ko + 8);
            cp16(sb + STAGE_B + dA1, Bg1 + ko);  cp16(sb + STAGE_B + dA1 + 16, Bg1 + ko + 8);
            CP_COMMIT();
        }
        const uint32_t sb = smb + (c & 1) * STAGE2_B;
        const uint32_t aB = sb + aRowOff;
        const uint32_t bB = sb + bRowOff;
#pragma unroll
        for (int ks = 0; ks < 4; ++ks) {
            uint32_t b[2][4];
            ldmx4(b[0], bB + ks * 32);
            ldmx4(b[1], bB + 16 * (SSTR * 2) + ks * 32);
#pragma unroll
            for (int mt = 0; mt < 4; ++mt) {
                uint32_t a[4];
                ldmx4(a, aB + mt * 16 * (SSTR * 2) + ks * 32);
                mma_f16(acc[mt][0], a, b[0][0], b[0][2]);
                mma_f16(acc[mt][1], a, b[0][1], b[0][3]);
                mma_f16(acc[mt][2], a, b[1][0], b[1][2]);
                mma_f16(acc[mt][3], a, b[1][1], b[1][3]);
            }
        }
    }
}

__device__ __forceinline__ void hg_loop_f16(uint32_t smb, const __half* __restrict__ A,
                                            const __half* __restrict__ BT, int K,
                                            int m0, int n0, uint32_t hacc[4][4][2])
{
    const int tid  = threadIdx.x;
    const int lane = tid & 31;
    const int wid  = tid >> 5;
    const int warp_m = wid & 1, warp_n = wid >> 1;
    const int srow = tid >> 2;
    const int sco  = (tid & 3) * 16;
    const __half* Ag0 = A + (long)(m0 + srow) * K + sco;
    const __half* Ag1 = A + (long)(m0 + srow + 64) * K + sco;
    const __half* Bg0 = BT + (long)(n0 + srow) * K + sco;
    const __half* Bg1 = BT + (long)(n0 + srow + 64) * K + sco;
    const uint32_t dA0 = srow * (SSTR * 2) + (tid & 3) * 32;
    const uint32_t dA1 = (srow + 64) * (SSTR * 2) + (tid & 3) * 32;
    const uint32_t aRowOff = (warp_m * 64 + (lane & 15)) * (SSTR * 2) + (lane >> 4) * 16;
    const uint32_t bRowOff = STAGE_B + (warp_n * 32 + (lane & 15)) * (SSTR * 2) + (lane >> 4) * 16;

#pragma unroll
    for (int i = 0; i < 4; i++)
#pragma unroll
        for (int j = 0; j < 4; j++) { hacc[i][j][0] = 0u; hacc[i][j][1] = 0u; }

    const int nc = K >> 6;
    {
        cp16(smb + dA0, Ag0);            cp16(smb + dA0 + 16, Ag0 + 8);
        cp16(smb + dA1, Ag1);            cp16(smb + dA1 + 16, Ag1 + 8);
        cp16(smb + STAGE_B + dA0, Bg0);  cp16(smb + STAGE_B + dA0 + 16, Bg0 + 8);
        cp16(smb + STAGE_B + dA1, Bg1);  cp16(smb + STAGE_B + dA1 + 16, Bg1 + 8);
        CP_COMMIT();
    }
#pragma unroll 1
    for (int c = 0; c < nc; ++c) {
        CP_WAIT0();
        __syncthreads();
        if (c + 1 < nc) {
            const uint32_t sb = smb + ((c + 1) & 1) * STAGE2_B;
            const long ko = (long)(c + 1) * 64;
            cp16(sb + dA0, Ag0 + ko);            cp16(sb + dA0 + 16, Ag0 + ko + 8);
            cp16(sb + dA1, Ag1 + ko);            cp16(sb + dA1 + 16, Ag1 + ko + 8);
            cp16(sb + STAGE_B + dA0, Bg0 + ko);  cp16(sb + STAGE_B + dA0 + 16, Bg0 + ko + 8);
            cp16(sb + STAGE_B + dA1, Bg1 + ko);  cp16(sb + STAGE_B + dA1 + 16, Bg1 + ko + 8);
            CP_COMMIT();
        }
        const uint32_t sb = smb + (c & 1) * STAGE2_B;
        const uint32_t aB = sb + aRowOff;
        const uint32_t bB = sb + bRowOff;
#pragma unroll
        for (int ks = 0; ks < 4; ++ks) {
            uint32_t b[2][4];
            ldmx4(b[0], bB + ks * 32);
            ldmx4(b[1], bB + 16 * (SSTR * 2) + ks * 32);
#pragma unroll
            for (int mt = 0; mt < 4; ++mt) {
                uint32_t a[4];
                ldmx4(a, aB + mt * 16 * (SSTR * 2) + ks * 32);
                mma_h16(hacc[mt][0], a, b[0][0], b[0][2]);
                mma_h16(hacc[mt][1], a, b[0][1], b[0][3]);
                mma_h16(hacc[mt][2], a, b[1][0], b[1][2]);
                mma_h16(hacc[mt][3], a, b[1][1], b[1][3]);
            }
        }
    }
}

// ---------- single-stage K=128 f16-accum loop: one wait, one barrier ----------
__device__ __forceinline__ void hg_loop_f16_k128(uint32_t smb, const __half* __restrict__ A,
                                                 const __half* __restrict__ BT,
                                                 int m0, int n0, uint32_t hacc[4][4][2])
{
    const int tid  = threadIdx.x;
    const int lane = tid & 31;
    const int wid  = tid >> 5;
    const int warp_m = wid & 1, warp_n = wid >> 1;
    const int srow = tid >> 2;
    const int sco  = (tid & 3) * 32;                 // halfs (64B per thread-row-slice)
    const __half* Ag0 = A + (long)(m0 + srow) * 128 + sco;
    const __half* Ag1 = A + (long)(m0 + srow + 64) * 128 + sco;
    const __half* Bg0 = BT + (long)(n0 + srow) * 128 + sco;
    const __half* Bg1 = BT + (long)(n0 + srow + 64) * 128 + sco;
    const uint32_t dA0 = srow * (SSTR2 * 2) + (tid & 3) * 64;
    const uint32_t dA1 = (srow + 64) * (SSTR2 * 2) + (tid & 3) * 64;
    const uint32_t aRowOff = (warp_m * 64 + (lane & 15)) * (SSTR2 * 2) + (lane >> 4) * 16;
    const uint32_t bRowOff = A128_B + (warp_n * 32 + (lane & 15)) * (SSTR2 * 2) + (lane >> 4) * 16;

#pragma unroll
    for (int i = 0; i < 4; i++)
#pragma unroll
        for (int j = 0; j < 4; j++) { hacc[i][j][0] = 0u; hacc[i][j][1] = 0u; }

#pragma unroll
    for (int u = 0; u < 4; ++u) {
        cp16(smb + dA0 + u * 16, Ag0 + u * 8);
        cp16(smb + dA1 + u * 16, Ag1 + u * 8);
        cp16(smb + A128_B + dA0 + u * 16, Bg0 + u * 8);
        cp16(smb + A128_B + dA1 + u * 16, Bg1 + u * 8);
    }
    CP_COMMIT();
    CP_WAIT0();
    __syncthreads();

    const uint32_t aB = smb + aRowOff;
    const uint32_t bB = smb + bRowOff;
#pragma unroll
    for (int ks = 0; ks < 8; ++ks) {
        uint32_t b[2][4];
        ldmx4(b[0], bB + ks * 32);
        ldmx4(b[1], bB + 16 * (SSTR2 * 2) + ks * 32);
#pragma unroll
        for (int mt = 0; mt < 4; ++mt) {
            uint32_t a[4];
            ldmx4(a, aB + mt * 16 * (SSTR2 * 2) + ks * 32);
            mma_h16(hacc[mt][0], a, b[0][0], b[0][2]);
            mma_h16(hacc[mt][1], a, b[0][1], b[0][3]);
            mma_h16(hacc[mt][2], a, b[1][0], b[1][2]);
            mma_h16(hacc[mt][3], a, b[1][1], b[1][3]);
        }
    }
}

// ====== merged launch 1: scores(+fused P1 softmax, raw ST) ∥ qW1T GEMM ======
__global__ __launch_bounds__(256, 2)
void k_score_qw(const __half* __restrict__ ihp, const __half* __restrict__ qhp,
                const __half* __restrict__ WT0,
                float* __restrict__ ST, __half* __restrict__ P1h,
                __half* __restrict__ qW1T,
                const unsigned int* __restrict__ qmask, float alpha)
{
    extern __shared__ __align__(16) char smx[];
    const uint32_t smb = smem_u32(smx);
    const int bid = blockIdx.x;
    const int tid = threadIdx.x;
    const int lane = tid & 31;
    const int wid = tid >> 5;
    const int gid = lane >> 2, tig = lane & 3;
    const int warp_m = wid & 1, warp_n = wid >> 1;

    if (bid < 256) {
        const int zb = bid >> 2;
        const int m0 = (bid & 3) * 128;
        float acc[4][4][4];
        hg_loop_f32(smb, ihp + (long)zb * NI * DD, qhp + (long)zb * NQ * DD,
                    DD, m0, 0, acc);

        __syncthreads();
        float* Ssm = (float*)smx;
        uint32_t* mkS = (uint32_t*)(smx + 128 * 129 * 4);
#pragma unroll
        for (int mt = 0; mt < 4; mt++)
#pragma unroll
            for (int r = 0; r < 2; r++) {
                int m = warp_m * 64 + mt * 16 + r * 8 + gid;
#pragma unroll
                for (int nt = 0; nt < 4; nt++) {
                    int n = warp_n * 32 + nt * 8 + tig * 2;
                    Ssm[m * 129 + n]     = acc[mt][nt][r * 2 + 0] * alpha;
                    Ssm[m * 129 + n + 1] = acc[mt][nt][r * 2 + 1] * alpha;
                }
            }
        if (tid < NQ) mkS[tid] = qmask[zb * NQ + tid];
        __syncthreads();

        {
            float* STb = ST + (long)zb * NQ * NI + m0;
            for (int idx = tid; idx < 128 * 128; idx += 256) {
                int n = idx >> 7, m = idx & 127;
                STb[(long)n * NI + m] = Ssm[m * 129 + n];
            }
        }
        __syncthreads();

        {
            const int m = tid >> 1;
            const int h = (tid & 1) * 64;
            float* row = Ssm + m * 129;
            float mx = -3.4e38f;
#pragma unroll 8
            for (int j = 0; j < 64; j++) {
                int n = h + j;
                float x = (mkS[n] != 0u) ? NEGV : row[n];
                row[n] = x;
                mx = fmaxf(mx, x);
            }
            mx = fmaxf(mx, __shfl_xor_sync(0xffffffffu, mx, 1));
            float sum = 0.f;
#pragma unroll 8
            for (int j = 0; j < 64; j++) {
                float e = __expf(row[h + j] - mx);
                row[h + j] = e;
                sum += e;
            }
            sum += __shfl_xor_sync(0xffffffffu, sum, 1);
            float inv = 1.f / sum;
            __half2* P = (__half2*)(P1h + (long)zb * NI * NQ + (long)(m0 + m) * NQ + h);
#pragma unroll 8
            for (int j = 0; j < 32; j++)
                P[j] = __floats2half2_rn(row[h + 2 * j] * inv, row[h + 2 * j + 1] * inv);
        }
    } else {
        const int t = bid - 256;
        const int zb = t / 10;
        const int m0 = (t % 10) * 128;
        uint32_t hacc[4][4][2];
        hg_loop_f16(smb, WT0, qhp + (long)zb * NQ * DD, DD, m0, 0, hacc);

        __half* Ch = qW1T + (long)zb * DH * NQ;
#pragma unroll
        for (int mt = 0; mt < 4; mt++)
#pragma unroll
            for (int r = 0; r < 2; r++) {
                long m = m0 + warp_m * 64 + mt * 16 + r * 8 + gid;
#pragma unroll
                for (int nt = 0; nt < 4; nt++) {
                    int n = warp_n * 32 + nt * 8 + tig * 2;
                    *(uint32_t*)(Ch + m * NQ + n) = hacc[mt][nt][r];
                }
            }
    }
}

// ====== latt GEMM (f16 accum, logit-only consumer): latth = P2 @ i ======
__global__ __launch_bounds__(256, 3)
void k_latt(const __half* __restrict__ P2h, const __half* __restrict__ ihT,
            __half* __restrict__ latth)
{
    extern __shared__ __align__(16) char smx[];
    const uint32_t smb = smem_u32(smx);
    const int zb = blockIdx.z;
    const int tid = threadIdx.x;
    const int lane = tid & 31;
    const int wid = tid >> 5;
    const int gid = lane >> 2, tig = lane & 3;
    const int warp_m = wid & 1, warp_n = wid >> 1;
    const int n0 = blockIdx.x * 128;

    uint32_t hacc[4][4][2];
    hg_loop_f16(smb, P2h + (long)zb * NQ * NI, ihT + (long)zb * DD * NI,
                NI, 0, n0, hacc);

    __half* Ch = latth + (long)zb * NQ * DD;
#pragma unroll
    for (int mt = 0; mt < 4; mt++) {
#pragma unroll
        for (int r = 0; r < 2; r++) {
            long m = warp_m * 64 + mt * 16 + r * 8 + gid;
#pragma unroll
            for (int nt = 0; nt < 4; nt++) {
                int n = n0 + warp_n * 32 + nt * 8 + tig * 2;
                *(uint32_t*)(Ch + m * DD + n) = hacc[mt][nt][r];
            }
        }
    }
}

// ====== merged launch 2: G2 logits_i (single-stage K=128) ∥ l-hidden logits ======
__global__ __launch_bounds__(256, 3)
void k_logits(const __half* __restrict__ P1h, const __half* __restrict__ qW1T,
              const __half* __restrict__ latth, const __half* __restrict__ WT1,
              const float* __restrict__ lb1, const float* __restrict__ lW2,
              const float* __restrict__ ib1, const float* __restrict__ iW2,
              float* __restrict__ atti, float* __restrict__ attl)
{
    extern __shared__ __align__(16) char smx[];
    const uint32_t smb = smem_u32(smx);
    const int bid = blockIdx.x;
    const int tid = threadIdx.x;
    const int lane = tid & 31;
    const int wid = tid >> 5;
    const int gid = lane >> 2, tig = lane & 3;
    const int warp_m = wid & 1, warp_n = wid >> 1;

    uint32_t hacc[4][4][2];
    const float *b1, *w2;
    float* attOut;
    int m0, n0;
    if (bid < 2560) {
        const int zb = bid / 40, r = bid % 40;
        m0 = (r / 10) * 128;
        n0 = (r % 10) * 128;
        b1 = lb1; w2 = lW2;
        attOut = atti + (long)zb * NI;
        hg_loop_f16_k128(smb, P1h + (long)zb * NI * NQ,
                         qW1T + (long)zb * DH * NQ, m0, n0, hacc);
    } else {
        const int t = bid - 2560;
        m0 = (t / 10) * 128;
        n0 = (t % 10) * 128;
        b1 = ib1; w2 = iW2;
        attOut = attl;
        hg_loop_f16(smb, latth, WT1, DD, m0, n0, hacc);
    }

    float bv[8], wv[8];
#pragma unroll
    for (int nt = 0; nt < 4; nt++)
#pragma unroll
        for (int cc = 0; cc < 2; cc++) {
            int n = n0 + warp_n * 32 + nt * 8 + tig * 2 + cc;
            bv[nt * 2 + cc] = b1[n];
            wv[nt * 2 + cc] = w2[n];
        }
#pragma unroll
    for (int mt = 0; mt < 4; mt++) {
#pragma unroll
        for (int r = 0; r < 2; r++) {
            float s = 0.f;
#pragma unroll
            for (int nt = 0; nt < 4; nt++) {
                float2 v = __half22float2(*(__half2*)&hacc[mt][nt][r]);
                s += fmaxf(v.x + bv[nt * 2 + 0], 0.f) * wv[nt * 2 + 0];
                s += fmaxf(v.y + bv[nt * 2 + 1], 0.f) * wv[nt * 2 + 1];
            }
            s += __shfl_xor_sync(0xffffffffu, s, 1);
            s += __shfl_xor_sync(0xffffffffu, s, 2);
            if (tig == 0) {
                int m = m0 + warp_m * 64 + mt * 16 + r * 8 + gid;
                atomicAdd(attOut + m, s);
            }
        }
    }
}

// ====== merged prologue: conv_trans(i) ∥ conv_h(q) ∥ transpose_h2 ======
// blocks [0,20480): conv_trans ; [20480,25600): conv_h ; [25600,27200): transpose
__global__ void k_prep(const float* __restrict__ i_batch, const float* __restrict__ q_batch,
                       const float* __restrict__ lW1, const float* __restrict__ iW1,
                       __half* __restrict__ ih, __half* __restrict__ ihT,
                       __half* __restrict__ qh,
                       __half* __restrict__ WT0, __half* __restrict__ WT1)
{
    __shared__ float t[32][33];
    const int bid = blockIdx.x;
    const int tid = threadIdx.x;
    const int tx = tid & 31;
    const int ty = tid >> 5;

    if (bid < 20480) {
        // conv_trans: x=bid%20 (d0), y=(bid/20)%16 (s0), z=bid/320 (batch)
        const int d0 = (bid % 20) * 32;
        const int s0 = ((bid / 20) % 16) * 32;
        const long bo = (long)(bid / 320) * NI * DD;
        const float* X = i_batch + bo;
        __half* Xh = ih + bo;
        __half* XhT = ihT + bo;
#pragma unroll
        for (int i = ty; i < 32; i += 8) {
            float v = X[(long)(s0 + i) * DD + d0 + tx];
            t[i][tx] = v;
            Xh[(long)(s0 + i) * DD + d0 + tx] = __float2half(v);
        }
        __syncthreads();
#pragma unroll
        for (int i = ty; i < 32; i += 8)
            XhT[(long)(d0 + i) * NI + s0 + tx] = __float2half(t[tx][i]);
    } else if (bid < 25600) {
        const int i = (bid - 20480) * 256 + tid;   // float4 index
        float4 v = ((const float4*)q_batch)[i];
        __half2* o = (__half2*)qh;
        o[2 * i]     = __floats2half2_rn(v.x, v.y);
        o[2 * i + 1] = __floats2half2_rn(v.z, v.w);
    } else {
        const int t2 = bid - 25600;
        const int c0 = (t2 % 40) * 32;
        const int r0 = ((t2 / 40) % 20) * 32;
        const int z = t2 / 800;
        const float* W = z ? iW1 : lW1;
        __half* WT = z ? WT1 : WT0;
#pragma unroll
        for (int i = ty; i < 32; i += 8)
            t[i][tx] = W[(long)(r0 + i) * DH + c0 + tx];
        __syncthreads();
#pragma unroll
        for (int i = ty; i < 32; i += 8)
            WT[(long)(c0 + i) * DD + r0 + tx] = __float2half(t[tx][i]);
    }
}

// ---------------- final linears, both paths, one launch ----------------
__global__ __launch_bounds__(256, 2)
void gemm_final(const float* __restrict__ pool,
                const float* __restrict__ W0, const float* __restrict__ W1,
                const float* __restrict__ b0, const float* __restrict__ b1,
                float* __restrict__ out)
{
    __shared__ __align__(16) float As[16][128];
    __shared__ __align__(16) float Bs[16][128];

    const int z = blockIdx.z;
    const float* A  = pool + (long)z * BB * DD;
    const float* Bm = z ? W1 : W0;
    const float* bias = z ? b1 : b0;
    float* C = out + (long)z * BB * DD;

    const int M = BB, N = DD, K = DD;
    const int n0 = blockIdx.x * 128;
    const int tid = threadIdx.x;
    const int tx = tid & 15;
    const int ty = tid >> 4;

    float acc[8][8];
#pragma unroll
    for (int i = 0; i < 8; i++)
#pragma unroll
        for (int j = 0; j < 8; j++) acc[i][j] = 0.f;

    for (int k0 = 0; k0 < K; k0 += 16) {
#pragma unroll
        for (int i = 0; i < 2; i++) {
            int f  = tid + i * 256;
            int ml = f >> 2;
            int kl = (f & 3) << 2;
            float4 v = make_float4(0.f, 0.f, 0.f, 0.f);
            if (ml < M)
                v = *(const float4*)(A + (long)ml * K + (k0 + kl));
            As[kl + 0][ml] = v.x; As[kl + 1][ml] = v.y;
            As[kl + 2][ml] = v.z; As[kl + 3][ml] = v.w;
        }
#pragma unroll
        for (int i = 0; i < 2; i++) {
            int f  = tid + i * 256;
            int kl = f >> 5;
            int nl = (f & 31) << 2;
            float4 v = *(const float4*)(Bm + (long)(k0 + kl) * N + (n0 + nl));
            *(float4*)&Bs[kl][nl] = v;
        }
        __syncthreads();

#pragma unroll
        for (int kk = 0; kk < 16; kk++) {
            float a[8], b[8];
            *(float4*)&a[0] = *(const float4*)&As[kk][ty * 4];
            *(float4*)&a[4] = *(const float4*)&As[kk][64 + ty * 4];
            *(float4*)&b[0] = *(const float4*)&Bs[kk][tx * 4];
            *(float4*)&b[4] = *(const float4*)&Bs[kk][64 + tx * 4];
#pragma unroll
            for (int i = 0; i < 8; i++)
#pragma unroll
                for (int j = 0; j < 8; j++)
                    acc[i][j] = fmaf(a[i], b[j], acc[i][j]);
        }
        __syncthreads();
    }

#pragma unroll
    for (int i = 0; i < 8; i++) {
        int m = (i < 4) ? (ty * 4 + i) : (64 + ty * 4 + i - 4);
        if (m >= M) continue;
#pragma unroll
        for (int g = 0; g < 2; g++) {
            int n = n0 + g * 64 + tx * 4;
            float4 v;
            v.x = acc[i][g * 4 + 0] + bias[n];
            v.y = acc[i][g * 4 + 1] + bias[n + 1];
            v.z = acc[i][g * 4 + 2] + bias[n + 2];
            v.w = acc[i][g * 4 + 3] + bias[n + 3];
            *(float4*)(C + (long)m * N + n) = v;
        }
    }
}

// ---------------- masked row softmax (device helper) ----------------
__device__ __forceinline__ float warpMax(float v)
{
#pragma unroll
    for (int o = 16; o > 0; o >>= 1) v = fmaxf(v, __shfl_xor_sync(0xffffffffu, v, o));
    return v;
}
__device__ __forceinline__ float warpSum(float v)
{
#pragma unroll
    for (int o = 16; o > 0; o >>= 1) v += __shfl_xor_sync(0xffffffffu, v, o);
    return v;
}

__device__ __forceinline__ void softmax_row_body(
    float* __restrict__ prow, const unsigned int* __restrict__ mrow, int N,
    __half* __restrict__ pout, float* __restrict__ wout)
{
    const int tid = threadIdx.x;
    const int cnt = N >> 7;
    float v[4];
    float mx = -3.4e38f;
    for (int c = 0; c < cnt; c++) {
        int n = (c << 7) + tid;
        float x = prow[n];
        if (mrow[n] != 0u) x = NEGV;
        v[c] = x;
        mx = fmaxf(mx, x);
    }
    __shared__ float sr[4];
    float wm = warpMax(mx);
    if ((tid & 31) == 0) sr[tid >> 5] = wm;
    __syncthreads();
    mx = fmaxf(fmaxf(sr[0], sr[1]), fmaxf(sr[2], sr[3]));

    float sum = 0.f;
    for (int c = 0; c < cnt; c++) { v[c] = __expf(v[c] - mx); sum += v[c]; }
    __syncthreads();
    float ws = warpSum(sum);
    if ((tid & 31) == 0) sr[tid >> 5] = ws;
    __syncthreads();
    sum = sr[0] + sr[1] + sr[2] + sr[3];

    float inv = 1.f / sum;
    for (int c = 0; c < cnt; c++) {
        int n = (c << 7) + tid;
        float r = v[c] * inv;
        if (pout) pout[n] = __float2half(r);
        else      prow[n] = r;
        if (wout) wout[n] = r;
    }
}

__global__ void k_softmax_P2(float* __restrict__ ST,
                             const unsigned int* __restrict__ imask,
                             __half* __restrict__ P2h)
{
    const int row = blockIdx.x;
    const int bb = row / NQ;
    softmax_row_body(ST + (long)row * NI, imask + (long)bb * NI, NI,
                     P2h + (long)row * NI, nullptr);
}

__global__ void k_softmax_att(float* __restrict__ atti, float* __restrict__ attl,
                              const unsigned int* __restrict__ imask,
                              const unsigned int* __restrict__ qmask,
                              float* __restrict__ iw_out)
{
    const int bid = blockIdx.x;
    if (bid < BB) {
        softmax_row_body(atti + (long)bid * NI, imask + (long)bid * NI, NI,
                         nullptr, iw_out + (long)bid * NI);
    } else {
        const int b = bid - BB;
        softmax_row_body(attl + (long)b * NQ, qmask + (long)b * NQ, NQ,
                         nullptr, nullptr);
    }
}

__global__ void k_gemv_w(const __half* __restrict__ P1h, const __half* __restrict__ P2h,
                         const float* __restrict__ atti, const float* __restrict__ attl,
                         float* __restrict__ w1, float* __restrict__ w2v)
{
    const int bid = blockIdx.x;
    const __half* Pp;
    const float* a;
    float* wout;
    int Mterms, Kdim, b, k;
    if (bid < BB) {
        b = bid; k = threadIdx.x;
        Pp = P1h + (long)b * NI * NQ + k;
        a = atti + (long)b * NI;
        wout = w1 + (long)b * NQ + k;
        Mterms = NI; Kdim = NQ;
    } else {
        const int t = bid - BB;
        b = t >> 2; k = (t & 3) * 128 + threadIdx.x;
        Pp = P2h + (long)b * NQ * NI + k;
        a = attl + (long)b * NQ;
        wout = w2v + (long)b * NI + k;
        Mterms = NQ; Kdim = NI;
    }
    float s0 = 0.f, s1 = 0.f, s2 = 0.f, s3 = 0.f;
    for (int m = 0; m < Mterms; m += 4) {
        s0 = fmaf(a[m + 0], __half2float(Pp[(long)(m + 0) * Kdim]), s0);
        s1 = fmaf(a[m + 1], __half2float(Pp[(long)(m + 1) * Kdim]), s1);
        s2 = fmaf(a[m + 2], __half2float(Pp[(long)(m + 2) * Kdim]), s2);
        s3 = fmaf(a[m + 3], __half2float(Pp[(long)(m + 3) * Kdim]), s3);
    }
    *wout = (s0 + s1) + (s2 + s3);
}

__global__ void k_gemv_pool(const __half* __restrict__ qh, const __half* __restrict__ ih,
                            const float* __restrict__ w1, const float* __restrict__ w2v,
                            float* __restrict__ pool)
{
    const int bid = blockIdx.x;
    const __half* X;
    const float* wp;
    float* po;
    int Nterms, b, d;
    if (bid < 320) {
        b = bid / 5; d = (bid % 5) * 128 + threadIdx.x;
        X = qh + (long)b * NQ * DD + d;
        wp = w1 + (long)b * NQ;
        po = pool + (long)b * DD + d;
        Nterms = NQ;
    } else {
        const int t = bid - 320;
        b = t / 5; d = (t % 5) * 128 + threadIdx.x;
        X = ih + (long)b * NI * DD + d;
        wp = w2v + (long)b * NI;
        po = pool + (long)(BB + b) * DD + d;
        Nterms = NI;
    }
    float s0 = 0.f, s1 = 0.f, s2 = 0.f, s3 = 0.f;
    for (int k = 0; k < Nterms; k += 4) {
        s0 = fmaf(wp[k + 0], __half2float(X[(long)(k + 0) * DD]), s0);
        s1 = fmaf(wp[k + 1], __half2float(X[(long)(k + 1) * DD]), s1);
        s2 = fmaf(wp[k + 2], __half2float(X[(long)(k + 2) * DD]), s2);
        s3 = fmaf(wp[k + 3], __half2float(X[(long)(k + 3) * DD]), s3);
    }
    *po = (s0 + s1) + (s2 + s3);
}

// ---------------------------------- launch ----------------------------------
extern "C" void kernel_launch(void* const* d_in, const int* in_sizes, int n_in,
                              void* d_out, int out_size)
{
    const float* i_batch = (const float*)d_in[0];
    const float* q_batch = (const float*)d_in[1];
    const unsigned int* i_mask = (const unsigned int*)d_in[2];
    const unsigned int* q_mask = (const unsigned int*)d_in[3];
    const float* lW1 = (const float*)d_in[4];
    const float* lb1 = (const float*)d_in[5];
    const float* lW2 = (const float*)d_in[6];
    const float* lWm = (const float*)d_in[8];
    const float* lbm = (const float*)d_in[9];
    const float* iW1 = (const float*)d_in[10];
    const float* ib1 = (const float*)d_in[11];
    const float* iW2 = (const float*)d_in[12];
    const float* iWm = (const float*)d_in[14];
    const float* ibm = (const float*)d_in[15];
    float* out = (float*)d_out;

    float *ST, *atti, *attl, *w1, *w2v, *pool;
    __half *ih, *qh, *ihT, *P1h, *P2h, *latth, *qW1T, *WT0, *WT1;
    cudaGetSymbolAddress((void**)&ST, g_ST);
    cudaGetSymbolAddress((void**)&atti, g_atti);
    cudaGetSymbolAddress((void**)&attl, g_attl);
    cudaGetSymbolAddress((void**)&w1, g_w1);
    cudaGetSymbolAddress((void**)&w2v, g_w2v);
    cudaGetSymbolAddress((void**)&pool, g_pool);
    cudaGetSymbolAddress((void**)&ih, g_ih);
    cudaGetSymbolAddress((void**)&qh, g_qh);
    cudaGetSymbolAddress((void**)&ihT, g_ihT);
    cudaGetSymbolAddress((void**)&P1h, g_P1h);
    cudaGetSymbolAddress((void**)&P2h, g_P2h);
    cudaGetSymbolAddress((void**)&latth, g_latth);
    cudaGetSymbolAddress((void**)&qW1T, g_qW1T);
    cudaGetSymbolAddress((void**)&WT0, g_WT0);
    cudaGetSymbolAddress((void**)&WT1, g_WT1);

    cudaFuncSetAttribute(k_score_qw, cudaFuncAttributeMaxDynamicSharedMemorySize, HG_SMEM);
    cudaFuncSetAttribute(k_latt, cudaFuncAttributeMaxDynamicSharedMemorySize, HG_SMEM);
    cudaFuncSetAttribute(k_logits, cudaFuncAttributeMaxDynamicSharedMemorySize, HG_SMEM);

    const float SCALE = 0.039528470752104744f;  // 1/sqrt(640)

    // ---- merged prologue + zero-init ----
    k_prep<<<27200, 256>>>(i_batch, q_batch, lW1, iW1, ih, ihT, qh, WT0, WT1);
    cudaMemsetAsync(atti, 0, BB * NI * sizeof(float));
    cudaMemsetAsync(attl, 0, BB * NQ * sizeof(float));

    // ---- merged: scores(+P1 softmax, ST) ∥ qW1T ----
    k_score_qw<<<896, 256, HG_SMEM>>>(ih, qh, WT0, ST, P1h, qW1T, q_mask, SCALE);

    // ---- P2 = softmax(ST, i_mask); latth = (P2 @ i) ----
    k_softmax_P2<<<BB * NQ, 128>>>(ST, i_mask, P2h);
    k_latt<<<dim3(DD / 128, 1, BB), 256, HG_SMEM>>>(P2h, ihT, latth);

    // ---- merged: G2 logits_i (single-stage K=128) ∥ l-hidden logits ----
    k_logits<<<3200, 256, HG_SMEM>>>(P1h, qW1T, latth, WT1,
                                     lb1, lW2, ib1, iW2, atti, attl);

    // ---- merged attflat softmaxes (i path emits i_weight) ----
    k_softmax_att<<<2 * BB, 128>>>(atti, attl, i_mask, q_mask, out + 2 * BB * DD);

    // ---- merged gemvs ----
    k_gemv_w<<<BB + 4 * BB, 128>>>(P1h, P2h, atti, attl, w1, w2v);
    k_gemv_pool<<<640, 128>>>(qh, ih, w1, w2v, pool);

    // ---- final linears ----
    gemm_final<<<dim3(DD / 128, 1, 2), 256>>>(pool, lWm, iWm, lbm, ibm, out);
}

// round 17
// speedup vs baseline: 1.0344x; 1.0344x over previous
#include <cuda_runtime.h>
#include <cuda_fp16.h>
#include <math.h>
#include <stdint.h>

// Problem dims
#define BB 64
#define NI 512
#define NQ 128
#define DD 640
#define DH 1280
#define NEGV (-65504.0f)

// ---------------- scratch ----------------
__device__ float  g_ST[BB * NQ * NI];
__device__ float  g_atti[BB * NI];
__device__ float  g_attl[BB * NQ];
__device__ float  g_w1[BB * NQ];
__device__ float  g_w2v[BB * NI];
__device__ float  g_pool[2 * BB * DD];
__device__ __half g_ih[BB * NI * DD];
__device__ __half g_qh[BB * NQ * DD];
__device__ __half g_ihT[BB * DD * NI];
__device__ __half g_P1h[BB * NI * NQ];
__device__ __half g_P2h[BB * NQ * NI];
__device__ __half g_latth[BB * NQ * DD];
__device__ __half g_qW1T[BB * DH * NQ];
__device__ __half g_WT0[DH * DD];
__device__ __half g_WT1[DH * DD];

__device__ __forceinline__ uint32_t smem_u32(const void* p)
{
    uint32_t a;
    asm("{ .reg .u64 t; cvta.to.shared.u64 t, %1; cvt.u32.u64 %0, t; }" : "=r"(a) : "l"(p));
    return a;
}
__device__ __forceinline__ void ldmx4(uint32_t r[4], uint32_t addr)
{
    asm volatile("ldmatrix.sync.aligned.m8n8.x4.shared.b16 {%0,%1,%2,%3}, [%4];"
                 : "=r"(r[0]), "=r"(r[1]), "=r"(r[2]), "=r"(r[3]) : "r"(addr));
}
__device__ __forceinline__ void mma_f16(float c[4], const uint32_t a[4],
                                        uint32_t b0, uint32_t b1)
{
    asm volatile(
        "mma.sync.aligned.m16n8k16.row.col.f32.f16.f16.f32 "
        "{%0,%1,%2,%3}, {%4,%5,%6,%7}, {%8,%9}, {%0,%1,%2,%3};"
        : "+f"(c[0]), "+f"(c[1]), "+f"(c[2]), "+f"(c[3])
        : "r"(a[0]), "r"(a[1]), "r"(a[2]), "r"(a[3]), "r"(b0), "r"(b1));
}
__device__ __forceinline__ void mma_h16(uint32_t d[2], const uint32_t a[4],
                                        uint32_t b0, uint32_t b1)
{
    asm volatile(
        "mma.sync.aligned.m16n8k16.row.col.f16.f16.f16.f16 "
        "{%0,%1}, {%2,%3,%4,%5}, {%6,%7}, {%0,%1};"
        : "+r"(d[0]), "+r"(d[1])
        : "r"(a[0]), "r"(a[1]), "r"(a[2]), "r"(a[3]), "r"(b0), "r"(b1));
}
__device__ __forceinline__ void cp16(uint32_t dst, const void* src)
{
    asm volatile("cp.async.ca.shared.global [%0], [%1], 16;" :: "r"(dst), "l"(src));
}
#define CP_COMMIT() asm volatile("cp.async.commit_group;" ::: "memory")
#define CP_WAIT0()  asm volatile("cp.async.wait_group 0;" ::: "memory")

#define SSTR 72
#define STAGE_B (128 * SSTR * 2)
#define STAGE2_B (2 * STAGE_B)
#define HG_SMEM (2 * STAGE2_B)

// ---------- 2-stage cp.async mainloops (128x128 tile, BK=64) ----------
__device__ __forceinline__ void hg_loop_f32(uint32_t smb, const __half* __restrict__ A,
                                            const __half* __restrict__ BT, int K,
                                            int m0, int n0, float acc[4][4][4])
{
    const int tid  = threadIdx.x;
    const int lane = tid & 31;
    const int wid  = tid >> 5;
    const int warp_m = wid & 1, warp_n = wid >> 1;
    const int srow = tid >> 2;
    const int sco  = (tid & 3) * 16;
    const __half* Ag0 = A + (long)(m0 + srow) * K + sco;
    const __half* Ag1 = A + (long)(m0 + srow + 64) * K + sco;
    const __half* Bg0 = BT + (long)(n0 + srow) * K + sco;
    const __half* Bg1 = BT + (long)(n0 + srow + 64) * K + sco;
    const uint32_t dA0 = srow * (SSTR * 2) + (tid & 3) * 32;
    const uint32_t dA1 = (srow + 64) * (SSTR * 2) + (tid & 3) * 32;
    const uint32_t aRowOff = (warp_m * 64 + (lane & 15)) * (SSTR * 2) + (lane >> 4) * 16;
    const uint32_t bRowOff = STAGE_B + (warp_n * 32 + (lane & 15)) * (SSTR * 2) + (lane >> 4) * 16;

#pragma unroll
    for (int i = 0; i < 4; i++)
#pragma unroll
        for (int j = 0; j < 4; j++)
#pragma unroll
            for (int r = 0; r < 4; r++) acc[i][j][r] = 0.f;

    const int nc = K >> 6;
    {
        cp16(smb + dA0, Ag0);            cp16(smb + dA0 + 16, Ag0 + 8);
        cp16(smb + dA1, Ag1);            cp16(smb + dA1 + 16, Ag1 + 8);
        cp16(smb + STAGE_B + dA0, Bg0);  cp16(smb + STAGE_B + dA0 + 16, Bg0 + 8);
        cp16(smb + STAGE_B + dA1, Bg1);  cp16(smb + STAGE_B + dA1 + 16, Bg1 + 8);
        CP_COMMIT();
    }
#pragma unroll 1
    for (int c = 0; c < nc; ++c) {
        CP_WAIT0();
        __syncthreads();
        if (c + 1 < nc) {
            const uint32_t sb = smb + ((c + 1) & 1) * STAGE2_B;
            const long ko = (long)(c + 1) * 64;
            cp16(sb + dA0, Ag0 + ko);            cp16(sb + dA0 + 16, Ag0 + ko + 8);
            cp16(sb + dA1, Ag1 + ko);            cp16(sb + dA1 + 16, Ag1 + ko + 8);
            cp16(sb + STAGE_B + dA0, Bg0 + ko);  cp16(sb + STAGE_B + dA0 + 16, Bg0 + ko + 8);
            cp16(sb + STAGE_B + dA1, Bg1 + ko);  cp16(sb + STAGE_B + dA1 + 16, Bg1 + ko + 8);
            CP_COMMIT();
        }
        const uint32_t sb = smb + (c & 1) * STAGE2_B;
        const uint32_t aB = sb + aRowOff;
        const uint32_t bB = sb + bRowOff;
#pragma unroll
        for (int ks = 0; ks < 4; ++ks) {
            uint32_t b[2][4];
            ldmx4(b[0], bB + ks * 32);
            ldmx4(b[1], bB + 16 * (SSTR * 2) + ks * 32);
#pragma unroll
            for (int mt = 0; mt < 4; ++mt) {
                uint32_t a[4];
                ldmx4(a, aB + mt * 16 * (SSTR * 2) + ks * 32);
                mma_f16(acc[mt][0], a, b[0][0], b[0][2]);
                mma_f16(acc[mt][1], a, b[0][1], b[0][3]);
                mma_f16(acc[mt][2], a, b[1][0], b[1][2]);
                mma_f16(acc[mt][3], a, b[1][1], b[1][3]);
            }
        }
    }
}

__device__ __forceinline__ void hg_loop_f16(uint32_t smb, const __half* __restrict__ A,
                                            const __half* __restrict__ BT, int K,
                                            int m0, int n0, uint32_t hacc[4][4][2])
{
    const int tid  = threadIdx.x;
    const int lane = tid & 31;
    const int wid  = tid >> 5;
    const int warp_m = wid & 1, warp_n = wid >> 1;
    const int srow = tid >> 2;
    const int sco  = (tid & 3) * 16;
    const __half* Ag0 = A + (long)(m0 + srow) * K + sco;
    const __half* Ag1 = A + (long)(m0 + srow + 64) * K + sco;
    const __half* Bg0 = BT + (long)(n0 + srow) * K + sco;
    const __half* Bg1 = BT + (long)(n0 + srow + 64) * K + sco;
    const uint32_t dA0 = srow * (SSTR * 2) + (tid & 3) * 32;
    const uint32_t dA1 = (srow + 64) * (SSTR * 2) + (tid & 3) * 32;
    const uint32_t aRowOff = (warp_m * 64 + (lane & 15)) * (SSTR * 2) + (lane >> 4) * 16;
    const uint32_t bRowOff = STAGE_B + (warp_n * 32 + (lane & 15)) * (SSTR * 2) + (lane >> 4) * 16;

#pragma unroll
    for (int i = 0; i < 4; i++)
#pragma unroll
        for (int j = 0; j < 4; j++) { hacc[i][j][0] = 0u; hacc[i][j][1] = 0u; }

    const int nc = K >> 6;
    {
        cp16(smb + dA0, Ag0);            cp16(smb + dA0 + 16, Ag0 + 8);
        cp16(smb + dA1, Ag1);            cp16(smb + dA1 + 16, Ag1 + 8);
        cp16(smb + STAGE_B + dA0, Bg0);  cp16(smb + STAGE_B + dA0 + 16, Bg0 + 8);
        cp16(smb + STAGE_B + dA1, Bg1);  cp16(smb + STAGE_B + dA1 + 16, Bg1 + 8);
        CP_COMMIT();
    }
#pragma unroll 1
    for (int c = 0; c < nc; ++c) {
        CP_WAIT0();
        __syncthreads();
        if (c + 1 < nc) {
            const uint32_t sb = smb + ((c + 1) & 1) * STAGE2_B;
            const long ko = (long)(c + 1) * 64;
            cp16(sb + dA0, Ag0 + ko);            cp16(sb + dA0 + 16, Ag0 + ko + 8);
            cp16(sb + dA1, Ag1 + ko);            cp16(sb + dA1 + 16, Ag1 + ko + 8);
            cp16(sb + STAGE_B + dA0, Bg0 + ko);  cp16(sb + STAGE_B + dA0 + 16, Bg0 + ko + 8);
            cp16(sb + STAGE_B + dA1, Bg1 + ko);  cp16(sb + STAGE_B + dA1 + 16, Bg1 + ko + 8);
            CP_COMMIT();
        }
        const uint32_t sb = smb + (c & 1) * STAGE2_B;
        const uint32_t aB = sb + aRowOff;
        const uint32_t bB = sb + bRowOff;
#pragma unroll
        for (int ks = 0; ks < 4; ++ks) {
            uint32_t b[2][4];
            ldmx4(b[0], bB + ks * 32);
            ldmx4(b[1], bB + 16 * (SSTR * 2) + ks * 32);
#pragma unroll
            for (int mt = 0; mt < 4; ++mt) {
                uint32_t a[4];
                ldmx4(a, aB + mt * 16 * (SSTR * 2) + ks * 32);
                mma_h16(hacc[mt][0], a, b[0][0], b[0][2]);
                mma_h16(hacc[mt][1], a, b[0][1], b[0][3]);
                mma_h16(hacc[mt][2], a, b[1][0], b[1][2]);
                mma_h16(hacc[mt][3], a, b[1][1], b[1][3]);
            }
        }
    }
}

// epilogue helper: fused attflat logit reduction
__device__ __forceinline__ void logits_epilogue(uint32_t hacc[4][4][2],
                                                const float* __restrict__ b1,
                                                const float* __restrict__ w2,
                                                float* __restrict__ attOut,
                                                int m0, int n0)
{
    const int tid = threadIdx.x;
    const int lane = tid & 31;
    const int wid = tid >> 5;
    const int gid = lane >> 2, tig = lane & 3;
    const int warp_m = wid & 1, warp_n = wid >> 1;
    float bv[8], wv[8];
#pragma unroll
    for (int nt = 0; nt < 4; nt++)
#pragma unroll
        for (int cc = 0; cc < 2; cc++) {
            int n = n0 + warp_n * 32 + nt * 8 + tig * 2 + cc;
            bv[nt * 2 + cc] = b1[n];
            wv[nt * 2 + cc] = w2[n];
        }
#pragma unroll
    for (int mt = 0; mt < 4; mt++) {
#pragma unroll
        for (int r = 0; r < 2; r++) {
            float s = 0.f;
#pragma unroll
            for (int nt = 0; nt < 4; nt++) {
                float2 v = __half22float2(*(__half2*)&hacc[mt][nt][r]);
                s += fmaxf(v.x + bv[nt * 2 + 0], 0.f) * wv[nt * 2 + 0];
                s += fmaxf(v.y + bv[nt * 2 + 1], 0.f) * wv[nt * 2 + 1];
            }
            s += __shfl_xor_sync(0xffffffffu, s, 1);
            s += __shfl_xor_sync(0xffffffffu, s, 2);
            if (tig == 0) {
                int m = m0 + warp_m * 64 + mt * 16 + r * 8 + gid;
                atomicAdd(attOut + m, s);
            }
        }
    }
}

// ====== merged launch 1: scores(+fused P1 softmax, raw ST) ∥ qW1T GEMM ======
__global__ __launch_bounds__(256, 2)
void k_score_qw(const __half* __restrict__ ihp, const __half* __restrict__ qhp,
                const __half* __restrict__ WT0,
                float* __restrict__ ST, __half* __restrict__ P1h,
                __half* __restrict__ qW1T,
                const unsigned int* __restrict__ qmask, float alpha)
{
    extern __shared__ __align__(16) char smx[];
    const uint32_t smb = smem_u32(smx);
    const int bid = blockIdx.x;
    const int tid = threadIdx.x;
    const int lane = tid & 31;
    const int wid = tid >> 5;
    const int gid = lane >> 2, tig = lane & 3;
    const int warp_m = wid & 1, warp_n = wid >> 1;

    if (bid < 256) {
        const int zb = bid >> 2;
        const int m0 = (bid & 3) * 128;
        float acc[4][4][4];
        hg_loop_f32(smb, ihp + (long)zb * NI * DD, qhp + (long)zb * NQ * DD,
                    DD, m0, 0, acc);

        __syncthreads();
        float* Ssm = (float*)smx;
        uint32_t* mkS = (uint32_t*)(smx + 128 * 129 * 4);
#pragma unroll
        for (int mt = 0; mt < 4; mt++)
#pragma unroll
            for (int r = 0; r < 2; r++) {
                int m = warp_m * 64 + mt * 16 + r * 8 + gid;
#pragma unroll
                for (int nt = 0; nt < 4; nt++) {
                    int n = warp_n * 32 + nt * 8 + tig * 2;
                    Ssm[m * 129 + n]     = acc[mt][nt][r * 2 + 0] * alpha;
                    Ssm[m * 129 + n + 1] = acc[mt][nt][r * 2 + 1] * alpha;
                }
            }
        if (tid < NQ) mkS[tid] = qmask[zb * NQ + tid];
        __syncthreads();

        {
            float* STb = ST + (long)zb * NQ * NI + m0;
            for (int idx = tid; idx < 128 * 128; idx += 256) {
                int n = idx >> 7, m = idx & 127;
                STb[(long)n * NI + m] = Ssm[m * 129 + n];
            }
        }
        __syncthreads();

        {
            const int m = tid >> 1;
            const int h = (tid & 1) * 64;
            float* row = Ssm + m * 129;
            float mx = -3.4e38f;
#pragma unroll 8
            for (int j = 0; j < 64; j++) {
                int n = h + j;
                float x = (mkS[n] != 0u) ? NEGV : row[n];
                row[n] = x;
                mx = fmaxf(mx, x);
            }
            mx = fmaxf(mx, __shfl_xor_sync(0xffffffffu, mx, 1));
            float sum = 0.f;
#pragma unroll 8
            for (int j = 0; j < 64; j++) {
                float e = __expf(row[h + j] - mx);
                row[h + j] = e;
                sum += e;
            }
            sum += __shfl_xor_sync(0xffffffffu, sum, 1);
            float inv = 1.f / sum;
            __half2* P = (__half2*)(P1h + (long)zb * NI * NQ + (long)(m0 + m) * NQ + h);
#pragma unroll 8
            for (int j = 0; j < 32; j++)
                P[j] = __floats2half2_rn(row[h + 2 * j] * inv, row[h + 2 * j + 1] * inv);
        }
    } else {
        const int t = bid - 256;
        const int zb = t / 10;
        const int m0 = (t % 10) * 128;
        uint32_t hacc[4][4][2];
        hg_loop_f16(smb, WT0, qhp + (long)zb * NQ * DD, DD, m0, 0, hacc);

        __half* Ch = qW1T + (long)zb * DH * NQ;
#pragma unroll
        for (int mt = 0; mt < 4; mt++)
#pragma unroll
            for (int r = 0; r < 2; r++) {
                long m = m0 + warp_m * 64 + mt * 16 + r * 8 + gid;
#pragma unroll
                for (int nt = 0; nt < 4; nt++) {
                    int n = warp_n * 32 + nt * 8 + tig * 2;
                    *(uint32_t*)(Ch + m * NQ + n) = hacc[mt][nt][r];
                }
            }
    }
}

// ====== merged launch 2: latt (320 CTAs) ∥ G2 logits_i (2560 CTAs) ======
// latt: latth[zb] = P2h[zb] @ ihT[zb]^T (f16 out).  G2: logits_i via P1h @ qW1T^T.
__global__ __launch_bounds__(256, 3)
void k_latt_g2(const __half* __restrict__ P2h, const __half* __restrict__ ihT,
               __half* __restrict__ latth,
               const __half* __restrict__ P1h, const __half* __restrict__ qW1T,
               const float* __restrict__ lb1, const float* __restrict__ lW2,
               float* __restrict__ atti)
{
    extern __shared__ __align__(16) char smx[];
    const uint32_t smb = smem_u32(smx);
    const int bid = blockIdx.x;
    const int tid = threadIdx.x;
    const int lane = tid & 31;
    const int wid = tid >> 5;
    const int gid = lane >> 2, tig = lane & 3;
    const int warp_m = wid & 1, warp_n = wid >> 1;

    uint32_t hacc[4][4][2];
    if (bid < 320) {
        const int zb = bid / 5;
        const int n0 = (bid % 5) * 128;
        hg_loop_f16(smb, P2h + (long)zb * NQ * NI, ihT + (long)zb * DD * NI,
                    NI, 0, n0, hacc);
        __half* Ch = latth + (long)zb * NQ * DD;
#pragma unroll
        for (int mt = 0; mt < 4; mt++)
#pragma unroll
            for (int r = 0; r < 2; r++) {
                long m = warp_m * 64 + mt * 16 + r * 8 + gid;
#pragma unroll
                for (int nt = 0; nt < 4; nt++) {
                    int n = n0 + warp_n * 32 + nt * 8 + tig * 2;
                    *(uint32_t*)(Ch + m * DD + n) = hacc[mt][nt][r];
                }
            }
    } else {
        const int t = bid - 320;
        const int zb = t / 40, r = t % 40;
        const int m0 = (r / 10) * 128;
        const int n0 = (r % 10) * 128;
        hg_loop_f16(smb, P1h + (long)zb * NI * NQ,
                    qW1T + (long)zb * DH * NQ, NQ, m0, n0, hacc);
        logits_epilogue(hacc, lb1, lW2, atti + (long)zb * NI, m0, n0);
    }
}

// ====== l-hidden logits: attl via relu(latth @ WT1^T + ib1) @ iW2 ======
__global__ __launch_bounds__(256, 3)
void k_logits_l(const __half* __restrict__ latth, const __half* __restrict__ WT1,
                const float* __restrict__ ib1, const float* __restrict__ iW2,
                float* __restrict__ attl)
{
    extern __shared__ __align__(16) char smx[];
    const uint32_t smb = smem_u32(smx);
    const int bid = blockIdx.x;
    const int m0 = (bid / 10) * 128;
    const int n0 = (bid % 10) * 128;

    uint32_t hacc[4][4][2];
    hg_loop_f16(smb, latth, WT1, DD, m0, n0, hacc);
    logits_epilogue(hacc, ib1, iW2, attl, m0, n0);
}

// ====== merged prologue ======
__global__ void k_prep(const float* __restrict__ i_batch, const float* __restrict__ q_batch,
                       const float* __restrict__ lW1, const float* __restrict__ iW1,
                       __half* __restrict__ ih, __half* __restrict__ ihT,
                       __half* __restrict__ qh,
                       __half* __restrict__ WT0, __half* __restrict__ WT1)
{
    __shared__ float t[32][33];
    const int bid = blockIdx.x;
    const int tid = threadIdx.x;
    const int tx = tid & 31;
    const int ty = tid >> 5;

    if (bid < 20480) {
        const int d0 = (bid % 20) * 32;
        const int s0 = ((bid / 20) % 16) * 32;
        const long bo = (long)(bid / 320) * NI * DD;
        const float* X = i_batch + bo;
        __half* Xh = ih + bo;
        __half* XhT = ihT + bo;
#pragma unroll
        for (int i = ty; i < 32; i += 8) {
            float v = X[(long)(s0 + i) * DD + d0 + tx];
            t[i][tx] = v;
            Xh[(long)(s0 + i) * DD + d0 + tx] = __float2half(v);
        }
        __syncthreads();
#pragma unroll
        for (int i = ty; i < 32; i += 8)
            XhT[(long)(d0 + i) * NI + s0 + tx] = __float2half(t[tx][i]);
    } else if (bid < 25600) {
        const int i = (bid - 20480) * 256 + tid;
        float4 v = ((const float4*)q_batch)[i];
        __half2* o = (__half2*)qh;
        o[2 * i]     = __floats2half2_rn(v.x, v.y);
        o[2 * i + 1] = __floats2half2_rn(v.z, v.w);
    } else {
        const int t2 = bid - 25600;
        const int c0 = (t2 % 40) * 32;
        const int r0 = ((t2 / 40) % 20) * 32;
        const int z = t2 / 800;
        const float* W = z ? iW1 : lW1;
        __half* WT = z ? WT1 : WT0;
#pragma unroll
        for (int i = ty; i < 32; i += 8)
            t[i][tx] = W[(long)(r0 + i) * DH + c0 + tx];
        __syncthreads();
#pragma unroll
        for (int i = ty; i < 32; i += 8)
            WT[(long)(c0 + i) * DD + r0 + tx] = __float2half(t[tx][i]);
    }
}

// ---------------- final linears, both paths, one launch ----------------
__global__ __launch_bounds__(256, 2)
void gemm_final(const float* __restrict__ pool,
                const float* __restrict__ W0, const float* __restrict__ W1,
                const float* __restrict__ b0, const float* __restrict__ b1,
                float* __restrict__ out)
{
    __shared__ __align__(16) float As[16][128];
    __shared__ __align__(16) float Bs[16][128];

    const int z = blockIdx.z;
    const float* A  = pool + (long)z * BB * DD;
    const float* Bm = z ? W1 : W0;
    const float* bias = z ? b1 : b0;
    float* C = out + (long)z * BB * DD;

    const int M = BB, N = DD, K = DD;
    const int n0 = blockIdx.x * 128;
    const int tid = threadIdx.x;
    const int tx = tid & 15;
    const int ty = tid >> 4;

    float acc[8][8];
#pragma unroll
    for (int i = 0; i < 8; i++)
#pragma unroll
        for (int j = 0; j < 8; j++) acc[i][j] = 0.f;

    for (int k0 = 0; k0 < K; k0 += 16) {
#pragma unroll
        for (int i = 0; i < 2; i++) {
            int f  = tid + i * 256;
            int ml = f >> 2;
            int kl = (f & 3) << 2;
            float4 v = make_float4(0.f, 0.f, 0.f, 0.f);
            if (ml < M)
                v = *(const float4*)(A + (long)ml * K + (k0 + kl));
            As[kl + 0][ml] = v.x; As[kl + 1][ml] = v.y;
            As[kl + 2][ml] = v.z; As[kl + 3][ml] = v.w;
        }
#pragma unroll
        for (int i = 0; i < 2; i++) {
            int f  = tid + i * 256;
            int kl = f >> 5;
            int nl = (f & 31) << 2;
            float4 v = *(const float4*)(Bm + (long)(k0 + kl) * N + (n0 + nl));
            *(float4*)&Bs[kl][nl] = v;
        }
        __syncthreads();

#pragma unroll
        for (int kk = 0; kk < 16; kk++) {
            float a[8], b[8];
            *(float4*)&a[0] = *(const float4*)&As[kk][ty * 4];
            *(float4*)&a[4] = *(const float4*)&As[kk][64 + ty * 4];
            *(float4*)&b[0] = *(const float4*)&Bs[kk][tx * 4];
            *(float4*)&b[4] = *(const float4*)&Bs[kk][64 + tx * 4];
#pragma unroll
            for (int i = 0; i < 8; i++)
#pragma unroll
                for (int j = 0; j < 8; j++)
                    acc[i][j] = fmaf(a[i], b[j], acc[i][j]);
        }
        __syncthreads();
    }

#pragma unroll
    for (int i = 0; i < 8; i++) {
        int m = (i < 4) ? (ty * 4 + i) : (64 + ty * 4 + i - 4);
        if (m >= M) continue;
#pragma unroll
        for (int g = 0; g < 2; g++) {
            int n = n0 + g * 64 + tx * 4;
            float4 v;
            v.x = acc[i][g * 4 + 0] + bias[n];
            v.y = acc[i][g * 4 + 1] + bias[n + 1];
            v.z = acc[i][g * 4 + 2] + bias[n + 2];
            v.w = acc[i][g * 4 + 3] + bias[n + 3];
            *(float4*)(C + (long)m * N + n) = v;
        }
    }
}

// ---------------- masked row softmax ----------------
__device__ __forceinline__ float warpMax(float v)
{
#pragma unroll
    for (int o = 16; o > 0; o >>= 1) v = fmaxf(v, __shfl_xor_sync(0xffffffffu, v, o));
    return v;
}
__device__ __forceinline__ float warpSum(float v)
{
#pragma unroll
    for (int o = 16; o > 0; o >>= 1) v += __shfl_xor_sync(0xffffffffu, v, o);
    return v;
}

__device__ __forceinline__ void softmax_row_body(
    float* __restrict__ prow, const unsigned int* __restrict__ mrow, int N,
    __half* __restrict__ pout, float* __restrict__ wout)
{
    const int tid = threadIdx.x;
    const int cnt = N >> 7;
    float v[4];
    float mx = -3.4e38f;
    for (int c = 0; c < cnt; c++) {
        int n = (c << 7) + tid;
        float x = prow[n];
        if (mrow[n] != 0u) x = NEGV;
        v[c] = x;
        mx = fmaxf(mx, x);
    }
    __shared__ float sr[4];
    float wm = warpMax(mx);
    if ((tid & 31) == 0) sr[tid >> 5] = wm;
    __syncthreads();
    mx = fmaxf(fmaxf(sr[0], sr[1]), fmaxf(sr[2], sr[3]));

    float sum = 0.f;
    for (int c = 0; c < cnt; c++) { v[c] = __expf(v[c] - mx); sum += v[c]; }
    __syncthreads();
    float ws = warpSum(sum);
    if ((tid & 31) == 0) sr[tid >> 5] = ws;
    __syncthreads();
    sum = sr[0] + sr[1] + sr[2] + sr[3];

    float inv = 1.f / sum;
    for (int c = 0; c < cnt; c++) {
        int n = (c << 7) + tid;
        float r = v[c] * inv;
        if (pout) pout[n] = __float2half(r);
        else      prow[n] = r;
        if (wout) wout[n] = r;
    }
}

__global__ void k_softmax_P2(float* __restrict__ ST,
                             const unsigned int* __restrict__ imask,
                             __half* __restrict__ P2h)
{
    const int row = blockIdx.x;
    const int bb = row / NQ;
    softmax_row_body(ST + (long)row * NI, imask + (long)bb * NI, NI,
                     P2h + (long)row * NI, nullptr);
}

__global__ void k_softmax_att(float* __restrict__ atti, float* __restrict__ attl,
                              const unsigned int* __restrict__ imask,
                              const unsigned int* __restrict__ qmask,
                              float* __restrict__ iw_out)
{
    const int bid = blockIdx.x;
    if (bid < BB) {
        softmax_row_body(atti + (long)bid * NI, imask + (long)bid * NI, NI,
                         nullptr, iw_out + (long)bid * NI);
    } else {
        const int b = bid - BB;
        softmax_row_body(attl + (long)b * NQ, qmask + (long)b * NQ, NQ,
                         nullptr, nullptr);
    }
}

__global__ void k_gemv_w(const __half* __restrict__ P1h, const __half* __restrict__ P2h,
                         const float* __restrict__ atti, const float* __restrict__ attl,
                         float* __restrict__ w1, float* __restrict__ w2v)
{
    const int bid = blockIdx.x;
    const __half* Pp;
    const float* a;
    float* wout;
    int Mterms, Kdim, b, k;
    if (bid < BB) {
        b = bid; k = threadIdx.x;
        Pp = P1h + (long)b * NI * NQ + k;
        a = atti + (long)b * NI;
        wout = w1 + (long)b * NQ + k;
        Mterms = NI; Kdim = NQ;
    } else {
        const int t = bid - BB;
        b = t >> 2; k = (t & 3) * 128 + threadIdx.x;
        Pp = P2h + (long)b * NQ * NI + k;
        a = attl + (long)b * NQ;
        wout = w2v + (long)b * NI + k;
        Mterms = NQ; Kdim = NI;
    }
    float s0 = 0.f, s1 = 0.f, s2 = 0.f, s3 = 0.f;
    for (int m = 0; m < Mterms; m += 4) {
        s0 = fmaf(a[m + 0], __half2float(Pp[(long)(m + 0) * Kdim]), s0);
        s1 = fmaf(a[m + 1], __half2float(Pp[(long)(m + 1) * Kdim]), s1);
        s2 = fmaf(a[m + 2], __half2float(Pp[(long)(m + 2) * Kdim]), s2);
        s3 = fmaf(a[m + 3], __half2float(Pp[(long)(m + 3) * Kdim]), s3);
    }
    *wout = (s0 + s1) + (s2 + s3);
}

__global__ void k_gemv_pool(const __half* __restrict__ qh, const __half* __restrict__ ih,
                            const float* __restrict__ w1, const float* __restrict__ w2v,
                            float* __restrict__ pool)
{
    const int bid = blockIdx.x;
    const __half* X;
    const float* wp;
    float* po;
    int Nterms, b, d;
    if (bid < 320) {
        b = bid / 5; d = (bid % 5) * 128 + threadIdx.x;
        X = qh + (long)b * NQ * DD + d;
        wp = w1 + (long)b * NQ;
        po = pool + (long)b * DD + d;
        Nterms = NQ;
    } else {
        const int t = bid - 320;
        b = t / 5; d = (t % 5) * 128 + threadIdx.x;
        X = ih + (long)b * NI * DD + d;
        wp = w2v + (long)b * NI;
        po = pool + (long)(BB + b) * DD + d;
        Nterms = NI;
    }
    float s0 = 0.f, s1 = 0.f, s2 = 0.f, s3 = 0.f;
    for (int k = 0; k < Nterms; k += 4) {
        s0 = fmaf(wp[k + 0], __half2float(X[(long)(k + 0) * DD]), s0);
        s1 = fmaf(wp[k + 1], __half2float(X[(long)(k + 1) * DD]), s1);
        s2 = fmaf(wp[k + 2], __half2float(X[(long)(k + 2) * DD]), s2);
        s3 = fmaf(wp[k + 3], __half2float(X[(long)(k + 3) * DD]), s3);
    }
    *po = (s0 + s1) + (s2 + s3);
}

// ---------------------------------- launch ----------------------------------
extern "C" void kernel_launch(void* const* d_in, const int* in_sizes, int n_in,
                              void* d_out, int out_size)
{
    const float* i_batch = (const float*)d_in[0];
    const float* q_batch = (const float*)d_in[1];
    const unsigned int* i_mask = (const unsigned int*)d_in[2];
    const unsigned int* q_mask = (const unsigned int*)d_in[3];
    const float* lW1 = (const float*)d_in[4];
    const float* lb1 = (const float*)d_in[5];
    const float* lW2 = (const float*)d_in[6];
    const float* lWm = (const float*)d_in[8];
    const float* lbm = (const float*)d_in[9];
    const float* iW1 = (const float*)d_in[10];
    const float* ib1 = (const float*)d_in[11];
    const float* iW2 = (const float*)d_in[12];
    const float* iWm = (const float*)d_in[14];
    const float* ibm = (const float*)d_in[15];
    float* out = (float*)d_out;

    float *ST, *atti, *attl, *w1, *w2v, *pool;
    __half *ih, *qh, *ihT, *P1h, *P2h, *latth, *qW1T, *WT0, *WT1;
    cudaGetSymbolAddress((void**)&ST, g_ST);
    cudaGetSymbolAddress((void**)&atti, g_atti);
    cudaGetSymbolAddress((void**)&attl, g_attl);
    cudaGetSymbolAddress((void**)&w1, g_w1);
    cudaGetSymbolAddress((void**)&w2v, g_w2v);
    cudaGetSymbolAddress((void**)&pool, g_pool);
    cudaGetSymbolAddress((void**)&ih, g_ih);
    cudaGetSymbolAddress((void**)&qh, g_qh);
    cudaGetSymbolAddress((void**)&ihT, g_ihT);
    cudaGetSymbolAddress((void**)&P1h, g_P1h);
    cudaGetSymbolAddress((void**)&P2h, g_P2h);
    cudaGetSymbolAddress((void**)&latth, g_latth);
    cudaGetSymbolAddress((void**)&qW1T, g_qW1T);
    cudaGetSymbolAddress((void**)&WT0, g_WT0);
    cudaGetSymbolAddress((void**)&WT1, g_WT1);

    cudaFuncSetAttribute(k_score_qw, cudaFuncAttributeMaxDynamicSharedMemorySize, HG_SMEM);
    cudaFuncSetAttribute(k_latt_g2, cudaFuncAttributeMaxDynamicSharedMemorySize, HG_SMEM);
    cudaFuncSetAttribute(k_logits_l, cudaFuncAttributeMaxDynamicSharedMemorySize, HG_SMEM);

    const float SCALE = 0.039528470752104744f;  // 1/sqrt(640)

    // ---- merged prologue + zero-init ----
    k_prep<<<27200, 256>>>(i_batch, q_batch, lW1, iW1, ih, ihT, qh, WT0, WT1);
    cudaMemsetAsync(atti, 0, BB * NI * sizeof(float));
    cudaMemsetAsync(attl, 0, BB * NQ * sizeof(float));

    // ---- merged: scores(+P1 softmax, ST) ∥ qW1T ----
    k_score_qw<<<896, 256, HG_SMEM>>>(ih, qh, WT0, ST, P1h, qW1T, q_mask, SCALE);

    // ---- P2 = softmax(ST, i_mask) ----
    k_softmax_P2<<<BB * NQ, 128>>>(ST, i_mask, P2h);

    // ---- merged: latt ∥ G2 logits_i (G2 independent of latth) ----
    k_latt_g2<<<2880, 256, HG_SMEM>>>(P2h, ihT, latth, P1h, qW1T, lb1, lW2, atti);

    // ---- l-hidden logits ----
    k_logits_l<<<640, 256, HG_SMEM>>>(latth, WT1, ib1, iW2, attl);

    // ---- merged attflat softmaxes (i path emits i_weight) ----
    k_softmax_att<<<2 * BB, 128>>>(atti, attl, i_mask, q_mask, out + 2 * BB * DD);

    // ---- merged gemvs ----
    k_gemv_w<<<BB + 4 * BB, 128>>>(P1h, P2h, atti, attl, w1, w2v);
    k_gemv_pool<<<640, 128>>>(qh, ih, w1, w2v, pool);

    // ---- final linears ----
    gemm_final<<<dim3(DD / 128, 1, 2), 256>>>(pool, lWm, iWm, lbm, ibm, out);
}